// round 4
// baseline (speedup 1.0000x reference)
#include <cuda_runtime.h>
#include <cuda_bf16.h>
#include <cstdint>
#include <cstddef>

// out[m,n] = sum_k Astack[m,k]*Bstack[n,k] + bias, M=8192 N=4096 K=12288 (bf16 hi/lo split)
static constexpr int M_TOT = 8192, KIN = 2048, K_TOT = 12288, N_TOT = 4096;
static constexpr size_t A_BLK = (size_t)M_TOT * KIN;

__device__ __nv_bfloat16 g_A4[4 * A_BLK];             // x planes: r_hi, r_lo, i_hi, i_lo
__device__ __nv_bfloat16 g_B[(size_t)N_TOT * K_TOT];  // stacked weights [n][k]

// ---------------- helpers ----------------
__device__ __forceinline__ uint32_t smem_u32(const void* p) {
    uint32_t a;
    asm("{ .reg .u64 t; cvta.to.shared.u64 t, %1; cvt.u32.u64 %0, t; }" : "=r"(a) : "l"(p));
    return a;
}
__device__ __forceinline__ void cp16(uint32_t dst, const void* src) {
    asm volatile("cp.async.cg.shared.global [%0], [%1], 16;" :: "r"(dst), "l"(src));
}
#define CP_COMMIT() asm volatile("cp.async.commit_group;" ::: "memory")
#define CP_WAIT2()  asm volatile("cp.async.wait_group 2;" ::: "memory")

#define LDSM4(R, addr) \
    asm volatile("ldmatrix.sync.aligned.m8n8.x4.shared.b16 {%0,%1,%2,%3}, [%4];" \
                 : "=r"((R)[0]), "=r"((R)[1]), "=r"((R)[2]), "=r"((R)[3]) : "r"(addr))

#define MMA16816(D, A, B0, B1) \
    asm volatile("mma.sync.aligned.m16n8k16.row.col.f32.bf16.bf16.f32 " \
                 "{%0,%1,%2,%3}, {%4,%5,%6,%7}, {%8,%9}, {%0,%1,%2,%3};" \
                 : "+f"((D)[0]), "+f"((D)[1]), "+f"((D)[2]), "+f"((D)[3]) \
                 : "r"((A)[0]), "r"((A)[1]), "r"((A)[2]), "r"((A)[3]), "r"(B0), "r"(B1))

// ---------------- builder: stacked B from TT cores (one CTA per out feature) ----------------
__device__ __forceinline__ __nv_bfloat16 bneg(__nv_bfloat16 v) {
    return __ushort_as_bfloat16(__bfloat16_as_ushort(v) ^ 0x8000u);
}
__global__ void build_B_kernel(const float* __restrict__ G1R, const float* __restrict__ G2R,
                               const float* __restrict__ G1I, const float* __restrict__ G2I) {
    __shared__ float s1r[64], s1i[64], s2r[512], s2i[512];
    const int o = blockIdx.x, o1 = o >> 7, o2 = o & 127, tid = threadIdx.x;
    if (tid < 64) { s1r[tid] = G1R[(o1 << 6) + tid]; s1i[tid] = G1I[(o1 << 6) + tid]; }
    for (int t = tid; t < 512; t += 256) {
        int r = t >> 7, i2 = t & 127;
        s2r[t] = G2R[((r << 7) + o2) * 128 + i2];
        s2i[t] = G2I[((r << 7) + o2) * 128 + i2];
    }
    __syncthreads();
    __nv_bfloat16* rowR = g_B + (size_t)o * K_TOT;
    __nv_bfloat16* rowI = g_B + (size_t)(o + 2048) * K_TOT;
    for (int i = tid; i < 2048; i += 256) {
        int i1 = i >> 7, i2 = i & 127;
        float wr = 0.f, wi = 0.f;
#pragma unroll
        for (int r = 0; r < 4; ++r) {
            wr += s1r[(r << 4) + i1] * s2r[(r << 7) + i2];
            wi += s1i[(r << 4) + i1] * s2i[(r << 7) + i2];
        }
        __nv_bfloat16 wrh = __float2bfloat16(wr);
        __nv_bfloat16 wrl = __float2bfloat16(wr - __bfloat162float(wrh));
        __nv_bfloat16 wih = __float2bfloat16(wi);
        __nv_bfloat16 wil = __float2bfloat16(wi - __bfloat162float(wih));
        rowR[i] = wrh;              rowR[2048 + i] = wrh;       rowR[4096 + i] = wrl;
        rowR[6144 + i] = bneg(wih); rowR[8192 + i] = bneg(wih); rowR[10240 + i] = bneg(wil);
        rowI[i] = wih;              rowI[2048 + i] = wih;       rowI[4096 + i] = wil;
        rowI[6144 + i] = wrh;       rowI[8192 + i] = wrh;       rowI[10240 + i] = wrl;
    }
}

// ---------------- builder: bf16 hi/lo planes of x ----------------
__device__ __forceinline__ void split16(float v, __nv_bfloat16& h, __nv_bfloat16& l) {
    h = __float2bfloat16(v);
    l = __float2bfloat16(v - __bfloat162float(h));
}
__global__ void build_A_kernel(const float* __restrict__ x) {
    size_t j = (size_t)blockIdx.x * 256 + threadIdx.x;   // 8192*512 threads
    size_t m = j >> 9;
    int c4 = (int)(j & 511) << 2;
    float4 xr = *(const float4*)(x + m * 4096 + c4);
    float4 xi = *(const float4*)(x + m * 4096 + 2048 + c4);
    __nv_bfloat16 h[4], l[4];
    size_t base = m * 2048 + c4;
    split16(xr.x, h[0], l[0]); split16(xr.y, h[1], l[1]);
    split16(xr.z, h[2], l[2]); split16(xr.w, h[3], l[3]);
    *(__nv_bfloat162*)(g_A4 + base)     = __halves2bfloat162(h[0], h[1]);
    *(__nv_bfloat162*)(g_A4 + base + 2) = __halves2bfloat162(h[2], h[3]);
    *(__nv_bfloat162*)(g_A4 + A_BLK + base)     = __halves2bfloat162(l[0], l[1]);
    *(__nv_bfloat162*)(g_A4 + A_BLK + base + 2) = __halves2bfloat162(l[2], l[3]);
    split16(xi.x, h[0], l[0]); split16(xi.y, h[1], l[1]);
    split16(xi.z, h[2], l[2]); split16(xi.w, h[3], l[3]);
    *(__nv_bfloat162*)(g_A4 + 2 * A_BLK + base)     = __halves2bfloat162(h[0], h[1]);
    *(__nv_bfloat162*)(g_A4 + 2 * A_BLK + base + 2) = __halves2bfloat162(h[2], h[3]);
    *(__nv_bfloat162*)(g_A4 + 3 * A_BLK + base)     = __halves2bfloat162(l[0], l[1]);
    *(__nv_bfloat162*)(g_A4 + 3 * A_BLK + base + 2) = __halves2bfloat162(l[2], l[3]);
}

// ---------------- main GEMM: 128x256 tile, BK=64, 4-stage cp.async, mma.sync ----------------
static constexpr int BM = 128, BN = 256, BK = 64, STAGES = 4;
static constexpr int A_STG = BM * BK * 2;              // 16384
static constexpr int STG = (BM + BN) * BK * 2;         // 49152
static constexpr int SMEM_DYN = STAGES * STG;          // 196608
static constexpr int NCHUNK = K_TOT / BK;              // 192

__constant__ int c_plane[6] = {0, 1, 0, 2, 3, 2};

__global__ void __launch_bounds__(256)
tt_gemm(const float* __restrict__ bias_r, const float* __restrict__ bias_i,
        float* __restrict__ out) {
    extern __shared__ char smraw[];
    const uint32_t sbase = smem_u32(smraw);
    const int tid = threadIdx.x, lane = tid & 31, wid = tid >> 5;
    const int wm = wid >> 2, wn = wid & 3;           // warp tile 64x64 in 2x4 grid

    // grouped raster: 64 m-blocks x 16 n-blocks, GROUP_M=8
    const int bid = blockIdx.x;
    const int group = bid >> 7;                      // / (8*16)
    const int rem = bid & 127;
    const int m0 = ((group << 3) + (rem & 7)) << 7;  // *128
    const int n0 = (rem >> 3) << 8;                  // *256

    const int ldr = tid >> 3, seg = tid & 7;

    auto load_chunk = [&](int c, int s) {
        const int kb = c >> 5, kc = c & 31;
        const __nv_bfloat16* aB = g_A4 + (size_t)c_plane[kb] * A_BLK +
                                  (size_t)m0 * KIN + (size_t)(kc << 6) + (seg << 3);
        const __nv_bfloat16* bB = g_B + (size_t)n0 * K_TOT + ((size_t)c << 6) + (seg << 3);
        const uint32_t sa = sbase + (uint32_t)s * STG;
        const uint32_t sb = sa + A_STG;
#pragma unroll
        for (int i = 0; i < 4; ++i) {
            int row = ldr + i * 32;
            uint32_t o = (uint32_t)(row * 128 + seg * 16);
            o ^= (o >> 3) & 0x70u;
            cp16(sa + o, aB + (size_t)row * KIN);
        }
#pragma unroll
        for (int i = 0; i < 8; ++i) {
            int row = ldr + i * 32;
            uint32_t o = (uint32_t)(row * 128 + seg * 16);
            o ^= (o >> 3) & 0x70u;
            cp16(sb + o, bB + (size_t)row * K_TOT);
        }
        CP_COMMIT();
    };

    float acc[4][8][4];
#pragma unroll
    for (int a = 0; a < 4; ++a)
#pragma unroll
        for (int b = 0; b < 8; ++b)
#pragma unroll
            for (int q = 0; q < 4; ++q) acc[a][b][q] = 0.f;

    load_chunk(0, 0);
    load_chunk(1, 1);
    load_chunk(2, 2);

#pragma unroll 1
    for (int c = 0; c < NCHUNK; ++c) {
        CP_WAIT2();
        __syncthreads();
        const int nc = c + STAGES - 1;
        if (nc < NCHUNK) load_chunk(nc, nc & 3); else CP_COMMIT();

        const uint32_t sa = sbase + (uint32_t)(c & 3) * STG;
        const uint32_t sb = sa + A_STG;
        uint32_t areg[4][4], breg[4][4];
#pragma unroll
        for (int ks = 0; ks < 4; ++ks) {
#pragma unroll
            for (int mi = 0; mi < 4; ++mi) {
                uint32_t o = (uint32_t)((wm * 64 + mi * 16 + (lane & 15)) * 128 +
                                        ks * 32 + ((lane >> 4) << 4));
                o ^= (o >> 3) & 0x70u;
                LDSM4(areg[mi], sa + o);
            }
#pragma unroll
            for (int p = 0; p < 4; ++p) {
                uint32_t row = (uint32_t)(wn * 64 + p * 16 + ((lane >> 4) << 3) + (lane & 7));
                uint32_t o = row * 128 + (uint32_t)(ks * 32 + (((lane >> 3) & 1) << 4));
                o ^= (o >> 3) & 0x70u;
                LDSM4(breg[p], sb + o);
            }
#pragma unroll
            for (int mi = 0; mi < 4; ++mi)
#pragma unroll
                for (int ni = 0; ni < 8; ++ni) {
                    const uint32_t* bp = &breg[ni >> 1][(ni & 1) << 1];
                    MMA16816(acc[mi][ni], areg[mi], bp[0], bp[1]);
                }
        }
    }

    // epilogue: acc + bias -> out (tile is entirely real or entirely imag half)
    const float* bb = (n0 < 2048) ? (bias_r + n0) : (bias_i + (n0 - 2048));
#pragma unroll
    for (int mi = 0; mi < 4; ++mi) {
        const int r0 = m0 + wm * 64 + mi * 16 + (lane >> 2);
#pragma unroll
        for (int ni = 0; ni < 8; ++ni) {
            const int col = wn * 64 + ni * 8 + ((lane & 3) << 1);
            const float b0 = bb[col], b1 = bb[col + 1];
            float2 v0 = { acc[mi][ni][0] + b0, acc[mi][ni][1] + b1 };
            float2 v1 = { acc[mi][ni][2] + b0, acc[mi][ni][3] + b1 };
            *(float2*)(out + (size_t)r0 * 4096 + n0 + col) = v0;
            *(float2*)(out + (size_t)(r0 + 8) * 4096 + n0 + col) = v1;
        }
    }
}

// ---------------- launch ----------------
extern "C" void kernel_launch(void* const* d_in, const int* in_sizes, int n_in,
                              void* d_out, int out_size) {
    const float* x   = (const float*)d_in[0];
    const float* G1R = (const float*)d_in[1];
    const float* G2R = (const float*)d_in[2];
    const float* G1I = (const float*)d_in[3];
    const float* G2I = (const float*)d_in[4];
    const float* br  = (const float*)d_in[5];
    const float* bi  = (const float*)d_in[6];
    float* out = (float*)d_out;

    cudaFuncSetAttribute(tt_gemm, cudaFuncAttributeMaxDynamicSharedMemorySize, SMEM_DYN);

    build_B_kernel<<<2048, 256>>>(G1R, G2R, G1I, G2I);
    build_A_kernel<<<16384, 256>>>(x);
    tt_gemm<<<(M_TOT / BM) * (N_TOT / BN), 256, SMEM_DYN>>>(br, bi, out);
}

// round 5
// speedup vs baseline: 1.2039x; 1.2039x over previous
#include <cuda_runtime.h>
#include <cuda_bf16.h>
#include <cstdint>
#include <cstddef>

// Karatsuba complex linear:
//   t1=(x_r+x_i)Wr, t2=x_r(Wi-Wr), t3=x_i(Wr+Wi); out_r=t1-t3+br, out_i=t1+t2+bi
// One stacked GEMM: M=8192, N=6144 ([t1|t2|t3]), K=6144 (3-term bf16 hi/lo split)
static constexpr int M_TOT = 8192, KIN = 2048, K_TOT = 6144, N_TOT = 6144;
static constexpr size_t A_BLK = (size_t)M_TOT * KIN;

__device__ __nv_bfloat16 g_A6[6 * A_BLK];             // xr_hi,xr_lo,xi_hi,xi_lo,s_hi,s_lo
__device__ __nv_bfloat16 g_B[(size_t)N_TOT * K_TOT];  // stacked weights [n][k]
__device__ float g_T[(size_t)M_TOT * N_TOT];          // t1|t2|t3

// ---------------- helpers ----------------
__device__ __forceinline__ uint32_t smem_u32(const void* p) {
    uint32_t a;
    asm("{ .reg .u64 t; cvta.to.shared.u64 t, %1; cvt.u32.u64 %0, t; }" : "=r"(a) : "l"(p));
    return a;
}
__device__ __forceinline__ void cp16(uint32_t dst, const void* src) {
    asm volatile("cp.async.cg.shared.global [%0], [%1], 16;" :: "r"(dst), "l"(src));
}
#define CP_COMMIT() asm volatile("cp.async.commit_group;" ::: "memory")
#define CP_WAIT2()  asm volatile("cp.async.wait_group 2;" ::: "memory")

#define LDSM4(R, addr) \
    asm volatile("ldmatrix.sync.aligned.m8n8.x4.shared.b16 {%0,%1,%2,%3}, [%4];" \
                 : "=r"((R)[0]), "=r"((R)[1]), "=r"((R)[2]), "=r"((R)[3]) : "r"(addr))

#define MMA16816(D, A, B0, B1) \
    asm volatile("mma.sync.aligned.m16n8k16.row.col.f32.bf16.bf16.f32 " \
                 "{%0,%1,%2,%3}, {%4,%5,%6,%7}, {%8,%9}, {%0,%1,%2,%3};" \
                 : "+f"((D)[0]), "+f"((D)[1]), "+f"((D)[2]), "+f"((D)[3]) \
                 : "r"((A)[0]), "r"((A)[1]), "r"((A)[2]), "r"((A)[3]), "r"(B0), "r"(B1))

// ---------------- builder: stacked B rows for t1/t2/t3 ----------------
__global__ void build_B_kernel(const float* __restrict__ G1R, const float* __restrict__ G2R,
                               const float* __restrict__ G1I, const float* __restrict__ G2I) {
    __shared__ float s1r[64], s1i[64], s2r[512], s2i[512];
    const int o = blockIdx.x, o1 = o >> 7, o2 = o & 127, tid = threadIdx.x;
    if (tid < 64) { s1r[tid] = G1R[(o1 << 6) + tid]; s1i[tid] = G1I[(o1 << 6) + tid]; }
    for (int t = tid; t < 512; t += 256) {
        int r = t >> 7, i2 = t & 127;
        s2r[t] = G2R[((r << 7) + o2) * 128 + i2];
        s2i[t] = G2I[((r << 7) + o2) * 128 + i2];
    }
    __syncthreads();
    __nv_bfloat16* row1 = g_B + (size_t)o * K_TOT;            // t1: Wr
    __nv_bfloat16* row2 = g_B + (size_t)(o + 2048) * K_TOT;   // t2: Wi-Wr
    __nv_bfloat16* row3 = g_B + (size_t)(o + 4096) * K_TOT;   // t3: Wr+Wi
    for (int i = tid; i < 2048; i += 256) {
        int i1 = i >> 7, i2 = i & 127;
        float wr = 0.f, wi = 0.f;
#pragma unroll
        for (int r = 0; r < 4; ++r) {
            wr += s1r[(r << 4) + i1] * s2r[(r << 7) + i2];
            wi += s1i[(r << 4) + i1] * s2i[(r << 7) + i2];
        }
        float d = wi - wr, s = wr + wi;
        __nv_bfloat16 h, l;
        h = __float2bfloat16(wr); l = __float2bfloat16(wr - __bfloat162float(h));
        row1[i] = h; row1[2048 + i] = h; row1[4096 + i] = l;
        h = __float2bfloat16(d);  l = __float2bfloat16(d - __bfloat162float(h));
        row2[i] = h; row2[2048 + i] = h; row2[4096 + i] = l;
        h = __float2bfloat16(s);  l = __float2bfloat16(s - __bfloat162float(h));
        row3[i] = h; row3[2048 + i] = h; row3[4096 + i] = l;
    }
}

// ---------------- builder: bf16 hi/lo planes of xr, xi, xr+xi ----------------
__device__ __forceinline__ void split16(float v, __nv_bfloat16& h, __nv_bfloat16& l) {
    h = __float2bfloat16(v);
    l = __float2bfloat16(v - __bfloat162float(h));
}
__global__ void build_A_kernel(const float* __restrict__ x) {
    size_t j = (size_t)blockIdx.x * 256 + threadIdx.x;   // 8192*512 threads
    size_t m = j >> 9;
    int c4 = (int)(j & 511) << 2;
    float4 xr = *(const float4*)(x + m * 4096 + c4);
    float4 xi = *(const float4*)(x + m * 4096 + 2048 + c4);
    float4 xs = { xr.x + xi.x, xr.y + xi.y, xr.z + xi.z, xr.w + xi.w };
    size_t base = m * 2048 + c4;
    __nv_bfloat16 h[4], l[4];
#define EMIT(v, P) \
    split16(v.x, h[0], l[0]); split16(v.y, h[1], l[1]); \
    split16(v.z, h[2], l[2]); split16(v.w, h[3], l[3]); \
    *(__nv_bfloat162*)(g_A6 + (P) * A_BLK + base)           = __halves2bfloat162(h[0], h[1]); \
    *(__nv_bfloat162*)(g_A6 + (P) * A_BLK + base + 2)       = __halves2bfloat162(h[2], h[3]); \
    *(__nv_bfloat162*)(g_A6 + (P + 1) * A_BLK + base)       = __halves2bfloat162(l[0], l[1]); \
    *(__nv_bfloat162*)(g_A6 + (P + 1) * A_BLK + base + 2)   = __halves2bfloat162(l[2], l[3]);
    EMIT(xr, 0)
    EMIT(xi, 2)
    EMIT(xs, 4)
#undef EMIT
}

// ---------------- main GEMM: 128x256 tile, BK=64, 4-stage cp.async, mma.sync ----------------
static constexpr int BM = 128, BN = 256, BK = 64, STAGES = 4;
static constexpr int A_STG = BM * BK * 2;              // 16384
static constexpr int STG = (BM + BN) * BK * 2;         // 49152
static constexpr int SMEM_DYN = STAGES * STG;          // 196608
static constexpr int NCHUNK = K_TOT / BK;              // 96

// plane[region][kb]: region = n0/2048 (t1->s, t2->xr, t3->xi); kb: hi,lo,hi
__constant__ int c_plane[3][3] = { {4, 5, 4}, {0, 1, 0}, {2, 3, 2} };

__global__ void __launch_bounds__(256)
tt_gemm() {
    extern __shared__ char smraw[];
    const uint32_t sbase = smem_u32(smraw);
    const int tid = threadIdx.x, lane = tid & 31, wid = tid >> 5;
    const int wm = wid >> 2, wn = wid & 3;           // warp tile 64x64 in 2x4 grid

    // grouped raster: 64 m-blocks x 24 n-blocks, GROUP_M=8
    const int bid = blockIdx.x;
    const int group = bid / 192;
    const int rem = bid % 192;
    const int m0 = (group * 8 + (rem & 7)) << 7;     // *128
    const int n0 = (rem >> 3) << 8;                  // *256
    const int region = n0 >> 11;

    const int ldr = tid >> 3, seg = tid & 7;

    auto load_chunk = [&](int c, int s) {
        const int kb = c >> 5, kc = c & 31;
        const __nv_bfloat16* aB = g_A6 + (size_t)c_plane[region][kb] * A_BLK +
                                  (size_t)m0 * KIN + (size_t)(kc << 6) + (seg << 3);
        const __nv_bfloat16* bB = g_B + (size_t)n0 * K_TOT + ((size_t)c << 6) + (seg << 3);
        const uint32_t sa = sbase + (uint32_t)s * STG;
        const uint32_t sb = sa + A_STG;
#pragma unroll
        for (int i = 0; i < 4; ++i) {
            int row = ldr + i * 32;
            uint32_t o = (uint32_t)(row * 128 + seg * 16);
            o ^= (o >> 3) & 0x70u;
            cp16(sa + o, aB + (size_t)row * KIN);
        }
#pragma unroll
        for (int i = 0; i < 8; ++i) {
            int row = ldr + i * 32;
            uint32_t o = (uint32_t)(row * 128 + seg * 16);
            o ^= (o >> 3) & 0x70u;
            cp16(sb + o, bB + (size_t)row * K_TOT);
        }
        CP_COMMIT();
    };

    float acc[4][8][4];
#pragma unroll
    for (int a = 0; a < 4; ++a)
#pragma unroll
        for (int b = 0; b < 8; ++b)
#pragma unroll
            for (int q = 0; q < 4; ++q) acc[a][b][q] = 0.f;

    load_chunk(0, 0);
    load_chunk(1, 1);
    load_chunk(2, 2);

#pragma unroll 1
    for (int c = 0; c < NCHUNK; ++c) {
        CP_WAIT2();
        __syncthreads();
        const int nc = c + STAGES - 1;
        if (nc < NCHUNK) load_chunk(nc, nc & 3); else CP_COMMIT();

        const uint32_t sa = sbase + (uint32_t)(c & 3) * STG;
        const uint32_t sb = sa + A_STG;
        uint32_t areg[4][4], breg[4][4];
#pragma unroll
        for (int ks = 0; ks < 4; ++ks) {
#pragma unroll
            for (int mi = 0; mi < 4; ++mi) {
                uint32_t o = (uint32_t)((wm * 64 + mi * 16 + (lane & 15)) * 128 +
                                        ks * 32 + ((lane >> 4) << 4));
                o ^= (o >> 3) & 0x70u;
                LDSM4(areg[mi], sa + o);
            }
#pragma unroll
            for (int p = 0; p < 4; ++p) {
                uint32_t row = (uint32_t)(wn * 64 + p * 16 + ((lane >> 4) << 3) + (lane & 7));
                uint32_t o = row * 128 + (uint32_t)(ks * 32 + (((lane >> 3) & 1) << 4));
                o ^= (o >> 3) & 0x70u;
                LDSM4(breg[p], sb + o);
            }
#pragma unroll
            for (int mi = 0; mi < 4; ++mi)
#pragma unroll
                for (int ni = 0; ni < 8; ++ni) {
                    const uint32_t* bp = &breg[ni >> 1][(ni & 1) << 1];
                    MMA16816(acc[mi][ni], areg[mi], bp[0], bp[1]);
                }
        }
    }

    // epilogue: acc -> g_T
#pragma unroll
    for (int mi = 0; mi < 4; ++mi) {
        const int r0 = m0 + wm * 64 + mi * 16 + (lane >> 2);
#pragma unroll
        for (int ni = 0; ni < 8; ++ni) {
            const int col = n0 + wn * 64 + ni * 8 + ((lane & 3) << 1);
            float2 v0 = { acc[mi][ni][0], acc[mi][ni][1] };
            float2 v1 = { acc[mi][ni][2], acc[mi][ni][3] };
            *(float2*)(g_T + (size_t)r0 * N_TOT + col) = v0;
            *(float2*)(g_T + (size_t)(r0 + 8) * N_TOT + col) = v1;
        }
    }
}

// ---------------- combine: out_r = t1 - t3 + br ; out_i = t1 + t2 + bi ----------------
__global__ void combine_kernel(const float* __restrict__ br, const float* __restrict__ bi,
                               float* __restrict__ out) {
    size_t j = (size_t)blockIdx.x * 256 + threadIdx.x;   // 8192*512 threads
    size_t m = j >> 9;
    int c4 = (int)(j & 511) << 2;
    const float* tr = g_T + m * (size_t)N_TOT + c4;
    float4 t1 = *(const float4*)(tr);
    float4 t2 = *(const float4*)(tr + 2048);
    float4 t3 = *(const float4*)(tr + 4096);
    float4 vbr = *(const float4*)(br + c4);
    float4 vbi = *(const float4*)(bi + c4);
    float4 vr = { t1.x - t3.x + vbr.x, t1.y - t3.y + vbr.y,
                  t1.z - t3.z + vbr.z, t1.w - t3.w + vbr.w };
    float4 vi = { t1.x + t2.x + vbi.x, t1.y + t2.y + vbi.y,
                  t1.z + t2.z + vbi.z, t1.w + t2.w + vbi.w };
    *(float4*)(out + m * 4096 + c4) = vr;
    *(float4*)(out + m * 4096 + 2048 + c4) = vi;
}

// ---------------- launch ----------------
extern "C" void kernel_launch(void* const* d_in, const int* in_sizes, int n_in,
                              void* d_out, int out_size) {
    const float* x   = (const float*)d_in[0];
    const float* G1R = (const float*)d_in[1];
    const float* G2R = (const float*)d_in[2];
    const float* G1I = (const float*)d_in[3];
    const float* G2I = (const float*)d_in[4];
    const float* br  = (const float*)d_in[5];
    const float* bi  = (const float*)d_in[6];
    float* out = (float*)d_out;

    cudaFuncSetAttribute(tt_gemm, cudaFuncAttributeMaxDynamicSharedMemorySize, SMEM_DYN);

    build_B_kernel<<<2048, 256>>>(G1R, G2R, G1I, G2I);
    build_A_kernel<<<16384, 256>>>(x);
    tt_gemm<<<(M_TOT / BM) * (N_TOT / BN), 256, SMEM_DYN>>>();
    combine_kernel<<<16384, 256>>>(br, bi, out);
}